// round 1
// baseline (speedup 1.0000x reference)
#include <cuda_runtime.h>
#include <cuda_bf16.h>

// CogitatDeepSetNorm collapses to scalar-per-row / scalar-per-segment math:
//   r_i   = rowsum(x_i)                               (per row)
//   seg_g = sum of r_i over segment g; cnt_g          (64 segments)
//   s_g   = relu(Gamma * seg_g/cnt_g)   (cnt>0)  else relu(Gamma * r_0)
//   o_i   = relu(Lambda * (r_i + 128*s_{sub[i]}))
//   out[i][0..255] = o_i
// Pure HBM streaming: read 128MB (x), write 128MB (out).

#define NROWS 131072
#define DIN 256
#define NSUB 64
#define ROWS_PER_BLOCK 128   // block = 256 threads = 8 warps, 16 rows/warp
#define BLOCK_THREADS 256
#define GRID_BLOCKS (NROWS / ROWS_PER_BLOCK)  // 1024

__device__ float g_rowsum[NROWS];
__device__ float g_segsum[NSUB];
__device__ float g_segcnt[NSUB];

__global__ void zero_seg_kernel() {
    int t = threadIdx.x;
    if (t < NSUB) { g_segsum[t] = 0.f; g_segcnt[t] = 0.f; }
}

__global__ __launch_bounds__(BLOCK_THREADS) void pass1_kernel(
    const float* __restrict__ x, const int* __restrict__ sub)
{
    __shared__ float ssum[NSUB];
    __shared__ float scnt[NSUB];
    int t = threadIdx.x;
    if (t < NSUB) { ssum[t] = 0.f; scnt[t] = 0.f; }
    __syncthreads();

    int warp = t >> 5, lane = t & 31;
    int row0 = blockIdx.x * ROWS_PER_BLOCK;

    #pragma unroll 1
    for (int r = warp; r < ROWS_PER_BLOCK; r += (BLOCK_THREADS >> 5)) {
        int row = row0 + r;
        const float4* p = reinterpret_cast<const float4*>(x + (size_t)row * DIN);
        float4 a = p[lane];
        float4 b = p[lane + 32];
        float s = (a.x + a.y) + (a.z + a.w) + (b.x + b.y) + (b.z + b.w);
        #pragma unroll
        for (int o = 16; o; o >>= 1) s += __shfl_xor_sync(0xffffffffu, s, o);
        if (lane == 0) {
            g_rowsum[row] = s;
            int sg = sub[row];
            atomicAdd(&ssum[sg], s);
            atomicAdd(&scnt[sg], 1.f);
        }
    }
    __syncthreads();
    if (t < NSUB && scnt[t] != 0.f) {
        atomicAdd(&g_segsum[t], ssum[t]);
        atomicAdd(&g_segcnt[t], scnt[t]);
    }
}

__global__ __launch_bounds__(BLOCK_THREADS) void pass2_kernel(
    const int* __restrict__ sub,
    const float* __restrict__ Gamma,
    const float* __restrict__ Lambda,
    float* __restrict__ out)
{
    __shared__ float s_tab[NSUB];
    int t = threadIdx.x;
    if (t < NSUB) {
        float cnt = g_segcnt[t];
        // torch fallback for empty group: mean = x[0] -> sum over dims = rowsum(x[0])
        float m = (cnt > 0.f) ? (g_segsum[t] / cnt) : g_rowsum[0];
        float sv = Gamma[0] * m;
        s_tab[t] = sv > 0.f ? sv : 0.f;
    }
    __syncthreads();

    float lam = Lambda[0];
    int warp = t >> 5, lane = t & 31;
    int row0 = blockIdx.x * ROWS_PER_BLOCK;

    #pragma unroll 1
    for (int r = warp; r < ROWS_PER_BLOCK; r += (BLOCK_THREADS >> 5)) {
        int row = row0 + r;
        float o = lam * (g_rowsum[row] + 128.f * s_tab[sub[row]]);
        o = o > 0.f ? o : 0.f;
        float4 v = make_float4(o, o, o, o);
        float4* p = reinterpret_cast<float4*>(out + (size_t)row * DIN);
        p[lane] = v;
        p[lane + 32] = v;
    }
}

extern "C" void kernel_launch(void* const* d_in, const int* in_sizes, int n_in,
                              void* d_out, int out_size)
{
    const float* x     = (const float*)d_in[0];
    const int*   sub   = (const int*)d_in[1];
    const float* Gamma = (const float*)d_in[2];
    const float* Lambda= (const float*)d_in[3];
    float* out = (float*)d_out;

    zero_seg_kernel<<<1, 64>>>();
    pass1_kernel<<<GRID_BLOCKS, BLOCK_THREADS>>>(x, sub);
    pass2_kernel<<<GRID_BLOCKS, BLOCK_THREADS>>>(sub, Gamma, Lambda, out);
}